// round 7
// baseline (speedup 1.0000x reference)
#include <cuda_runtime.h>
#include <math.h>
#include <stdint.h>

#define Bq 64
#define Sq 48
#define Tq 48
#define Eq 256
#define Hq 512
#define Vq 32000
#define H3 1536

// ---------------- scratch (device globals; no runtime allocation) -------------
__device__ __align__(16) float g_gi_enc[Bq * Sq * H3];        // 18.9 MB
__device__ __align__(16) float g_gi_dec[Bq * (Tq - 1) * H3];  // 18.5 MB
__device__ __align__(16) float g_h0[2][Bq * Hq];
__device__ __align__(16) float g_h1[2][Bq * Hq];
__device__ __align__(16) float g_n0[Bq * Hq];
__device__ __align__(16) float g_ys[(Tq - 1) * Bq * Hq];      // 6.2 MB

__device__ __forceinline__ float sigmoidf_(float x) { return 1.0f / (1.0f + expf(-x)); }

// ---------------- init kernels ------------------------------------------------
__global__ void zero_h_kernel() {
    int i = blockIdx.x * blockDim.x + threadIdx.x;
    if (i < Bq * Hq) { g_h0[0][i] = 0.f; g_h1[0][i] = 0.f; }
}

__global__ void zero_out0_kernel(float* __restrict__ out) {
    int i = blockIdx.x * blockDim.x + threadIdx.x;   // over B*V/4
    if (i < Bq * Vq / 4) {
        int b  = i / (Vq / 4);
        int v4 = i % (Vq / 4);
        reinterpret_cast<float4*>(out + (size_t)b * Tq * Vq)[v4] = make_float4(0.f, 0.f, 0.f, 0.f);
    }
}

// ---------------- gi0 = emb[tok] @ Wih^T + bih  (gathered SGEMM) --------------
// C[M x H3], A row m = emb[tokens[(m/rowlen)*rowstride + m%rowlen]] (len E)
// BM=64, BN=128, BK=8, 128 threads, 8x8 microtile.
__global__ __launch_bounds__(128) void embed_gi_kernel(
    const int* __restrict__ tokens, int rowlen, int rowstride,
    const float* __restrict__ emb,
    const float* __restrict__ W,    // [H3][E] row-major
    const float* __restrict__ bias, // [H3]
    int is_dec)
{
    __shared__ float As[8][64];
    __shared__ float Bs[8][128];
    float* __restrict__ out = is_dec ? g_gi_dec : g_gi_enc;

    const int tid = threadIdx.x;
    const int bm = blockIdx.y * 64;
    const int bn = blockIdx.x * 128;

    const int a_row = tid >> 1;            // 0..63
    const int a_col = (tid & 1) << 2;      // 0 or 4
    const int m = bm + a_row;
    const int tok = tokens[(m / rowlen) * rowstride + (m % rowlen)];
    const float* a_ptr = emb + (size_t)tok * Eq;
    const float* b_ptr = W + (size_t)(bn + tid) * Eq;

    const int rowT = tid >> 4;             // 0..7
    const int colT = tid & 15;             // 0..15

    float acc[8][8];
#pragma unroll
    for (int i = 0; i < 8; i++)
#pragma unroll
        for (int j = 0; j < 8; j++) acc[i][j] = 0.f;

    for (int k0 = 0; k0 < Eq; k0 += 8) {
        float4 av  = *reinterpret_cast<const float4*>(a_ptr + k0 + a_col);
        float4 bv0 = *reinterpret_cast<const float4*>(b_ptr + k0);
        float4 bv1 = *reinterpret_cast<const float4*>(b_ptr + k0 + 4);
        As[a_col + 0][a_row] = av.x; As[a_col + 1][a_row] = av.y;
        As[a_col + 2][a_row] = av.z; As[a_col + 3][a_row] = av.w;
        Bs[0][tid] = bv0.x; Bs[1][tid] = bv0.y; Bs[2][tid] = bv0.z; Bs[3][tid] = bv0.w;
        Bs[4][tid] = bv1.x; Bs[5][tid] = bv1.y; Bs[6][tid] = bv1.z; Bs[7][tid] = bv1.w;
        __syncthreads();
#pragma unroll
        for (int k = 0; k < 8; k++) {
            float a[8], b[8];
            *reinterpret_cast<float4*>(&a[0]) = *reinterpret_cast<const float4*>(&As[k][rowT * 8]);
            *reinterpret_cast<float4*>(&a[4]) = *reinterpret_cast<const float4*>(&As[k][rowT * 8 + 4]);
            *reinterpret_cast<float4*>(&b[0]) = *reinterpret_cast<const float4*>(&Bs[k][colT * 8]);
            *reinterpret_cast<float4*>(&b[4]) = *reinterpret_cast<const float4*>(&Bs[k][colT * 8 + 4]);
#pragma unroll
            for (int i = 0; i < 8; i++)
#pragma unroll
                for (int j = 0; j < 8; j++) acc[i][j] += a[i] * b[j];
        }
        __syncthreads();
    }

#pragma unroll
    for (int i = 0; i < 8; i++) {
        int mm = bm + rowT * 8 + i;
        float* op = out + (size_t)mm * H3 + bn + colT * 8;
        const float* bp = bias + bn + colT * 8;
#pragma unroll
        for (int j = 0; j < 8; j += 4) {
            float4 v;
            v.x = acc[i][j + 0] + bp[j + 0];
            v.y = acc[i][j + 1] + bp[j + 1];
            v.z = acc[i][j + 2] + bp[j + 2];
            v.w = acc[i][j + 3] + bp[j + 3];
            *reinterpret_cast<float4*>(op + j) = v;
        }
    }
}

// ---------------- GRU layer-0 step: gh = h@Whh^T fused with pointwise ---------
// warp -> (b, 4 consecutive j). 3 dots of length H per j.
__global__ __launch_bounds__(256) void gru_l0_step(
    int cur, int t, int is_dec,
    const float* __restrict__ Whh, const float* __restrict__ bhh,
    const int* __restrict__ slen)
{
    const int warp = (blockIdx.x * blockDim.x + threadIdx.x) >> 5;
    const int lane = threadIdx.x & 31;
    const int b = warp >> 7;                 // 128 warps per batch row
    const int jbase = (warp & 127) << 2;
    const float* hrow = g_h0[cur] + b * Hq;

    float acc[3][4];
#pragma unroll
    for (int g = 0; g < 3; g++)
#pragma unroll
        for (int jj = 0; jj < 4; jj++) acc[g][jj] = 0.f;

#pragma unroll
    for (int c = 0; c < 4; c++) {
        int idx = c * 128 + lane * 4;
        float4 h4 = *reinterpret_cast<const float4*>(hrow + idx);
#pragma unroll
        for (int g = 0; g < 3; g++) {
#pragma unroll
            for (int jj = 0; jj < 4; jj++) {
                float4 w4 = *reinterpret_cast<const float4*>(
                    Whh + (size_t)(g * Hq + jbase + jj) * Hq + idx);
                acc[g][jj] += h4.x * w4.x + h4.y * w4.y + h4.z * w4.z + h4.w * w4.w;
            }
        }
    }
#pragma unroll
    for (int g = 0; g < 3; g++)
#pragma unroll
        for (int jj = 0; jj < 4; jj++) {
            float v = acc[g][jj];
#pragma unroll
            for (int o = 16; o > 0; o >>= 1) v += __shfl_xor_sync(0xffffffffu, v, o);
            acc[g][jj] = v;
        }

    const float* gi = is_dec ? (g_gi_dec + (size_t)t * H3) : (g_gi_enc + (size_t)t * H3);
    const int bstride = is_dec ? (Tq - 1) * H3 : Sq * H3;

    // lanes 0..3 each finalize one j (accs are uniform across lanes after reduce)
    if (lane < 4) {
        const int jj = lane;
        const int j = jbase + jj;
        const bool msk = slen ? (t < slen[b]) : true;
        float gir = gi[(size_t)b * bstride + j];
        float giz = gi[(size_t)b * bstride + Hq + j];
        float gin = gi[(size_t)b * bstride + 2 * Hq + j];
        float r = sigmoidf_(gir + acc[0][jj] + bhh[j]);
        float z = sigmoidf_(giz + acc[1][jj] + bhh[Hq + j]);
        float n = tanhf(gin + r * (acc[2][jj] + bhh[2 * Hq + j]));
        float hp = hrow[j];
        float hn = (1.f - z) * n + z * hp;
        g_n0[b * Hq + j] = hn;                       // raw output feeds layer 1
        g_h0[cur ^ 1][b * Hq + j] = msk ? hn : hp;   // masked carry
    }
}

// ---------------- GRU layer-1 step: fused Wih1·n0 + Whh1·h1 + pointwise -------
__global__ __launch_bounds__(256) void gru_l1_step(
    int cur, int t, int is_dec,
    const float* __restrict__ Wih, const float* __restrict__ bih,
    const float* __restrict__ Whh, const float* __restrict__ bhh,
    const int* __restrict__ slen)
{
    const int warp = (blockIdx.x * blockDim.x + threadIdx.x) >> 5;
    const int lane = threadIdx.x & 31;
    const int b = warp >> 7;
    const int jbase = (warp & 127) << 2;
    const float* xrow = g_n0 + b * Hq;
    const float* hrow = g_h1[cur] + b * Hq;

    float acc[6][4];   // [0..2] = Wih gates vs x, [3..5] = Whh gates vs h
#pragma unroll
    for (int g = 0; g < 6; g++)
#pragma unroll
        for (int jj = 0; jj < 4; jj++) acc[g][jj] = 0.f;

#pragma unroll
    for (int c = 0; c < 4; c++) {
        int idx = c * 128 + lane * 4;
        float4 x4 = *reinterpret_cast<const float4*>(xrow + idx);
        float4 h4 = *reinterpret_cast<const float4*>(hrow + idx);
#pragma unroll
        for (int g = 0; g < 3; g++) {
#pragma unroll
            for (int jj = 0; jj < 4; jj++) {
                size_t ro = (size_t)(g * Hq + jbase + jj) * Hq + idx;
                float4 wi = *reinterpret_cast<const float4*>(Wih + ro);
                float4 wh = *reinterpret_cast<const float4*>(Whh + ro);
                acc[g][jj]     += x4.x * wi.x + x4.y * wi.y + x4.z * wi.z + x4.w * wi.w;
                acc[3 + g][jj] += h4.x * wh.x + h4.y * wh.y + h4.z * wh.z + h4.w * wh.w;
            }
        }
    }
#pragma unroll
    for (int g = 0; g < 6; g++)
#pragma unroll
        for (int jj = 0; jj < 4; jj++) {
            float v = acc[g][jj];
#pragma unroll
            for (int o = 16; o > 0; o >>= 1) v += __shfl_xor_sync(0xffffffffu, v, o);
            acc[g][jj] = v;
        }

    if (lane < 4) {
        const int jj = lane;
        const int j = jbase + jj;
        const bool msk = slen ? (t < slen[b]) : true;
        float r = sigmoidf_(acc[0][jj] + bih[j]          + acc[3][jj] + bhh[j]);
        float z = sigmoidf_(acc[1][jj] + bih[Hq + j]     + acc[4][jj] + bhh[Hq + j]);
        float n = tanhf(acc[2][jj] + bih[2 * Hq + j] + r * (acc[5][jj] + bhh[2 * Hq + j]));
        float hp = hrow[j];
        float hn = (1.f - z) * n + z * hp;
        g_h1[cur ^ 1][b * Hq + j] = msk ? hn : hp;
        if (is_dec) g_ys[((size_t)t * Bq + b) * Hq + j] = hn;
    }
}

// ---------------- final FC: logits = ys @ fc_W^T + fc_b, scattered ------------
// M=3008 (t*64+b), N=32000, K=512. BM=64, BN=128, BK=8, 128 threads, 8x8 tile.
// Grid: x walks M (47 tiles), y walks N (250 tiles) -> consecutive CTAs share
// the same W panel for better L2 reuse of the 65.5 MB weight matrix.
__global__ __launch_bounds__(128) void fc_kernel(
    const float* __restrict__ W,    // [V][H]
    const float* __restrict__ bias, // [V]
    float* __restrict__ out)
{
    __shared__ float As[8][64];
    __shared__ float Bs[8][128];

    const int tid = threadIdx.x;
    const int bm = blockIdx.x * 64;
    const int bn = blockIdx.y * 128;

    const int a_row = tid >> 1;
    const int a_col = (tid & 1) << 2;
    const float* a_ptr = g_ys + (size_t)(bm + a_row) * Hq;
    const float* b_ptr = W + (size_t)(bn + tid) * Hq;

    const int rowT = tid >> 4;
    const int colT = tid & 15;

    float acc[8][8];
#pragma unroll
    for (int i = 0; i < 8; i++)
#pragma unroll
        for (int j = 0; j < 8; j++) acc[i][j] = 0.f;

    for (int k0 = 0; k0 < Hq; k0 += 8) {
        float4 av  = *reinterpret_cast<const float4*>(a_ptr + k0 + a_col);
        float4 bv0 = __ldg(reinterpret_cast<const float4*>(b_ptr + k0));
        float4 bv1 = __ldg(reinterpret_cast<const float4*>(b_ptr + k0 + 4));
        As[a_col + 0][a_row] = av.x; As[a_col + 1][a_row] = av.y;
        As[a_col + 2][a_row] = av.z; As[a_col + 3][a_row] = av.w;
        Bs[0][tid] = bv0.x; Bs[1][tid] = bv0.y; Bs[2][tid] = bv0.z; Bs[3][tid] = bv0.w;
        Bs[4][tid] = bv1.x; Bs[5][tid] = bv1.y; Bs[6][tid] = bv1.z; Bs[7][tid] = bv1.w;
        __syncthreads();
#pragma unroll
        for (int k = 0; k < 8; k++) {
            float a[8], b[8];
            *reinterpret_cast<float4*>(&a[0]) = *reinterpret_cast<const float4*>(&As[k][rowT * 8]);
            *reinterpret_cast<float4*>(&a[4]) = *reinterpret_cast<const float4*>(&As[k][rowT * 8 + 4]);
            *reinterpret_cast<float4*>(&b[0]) = *reinterpret_cast<const float4*>(&Bs[k][colT * 8]);
            *reinterpret_cast<float4*>(&b[4]) = *reinterpret_cast<const float4*>(&Bs[k][colT * 8 + 4]);
#pragma unroll
            for (int i = 0; i < 8; i++)
#pragma unroll
                for (int j = 0; j < 8; j++) acc[i][j] += a[i] * b[j];
        }
        __syncthreads();
    }

#pragma unroll
    for (int i = 0; i < 8; i++) {
        int mm = bm + rowT * 8 + i;          // = t*64 + b
        int tt = mm >> 6;
        int bb = mm & 63;
        float* op = out + ((size_t)bb * Tq + (tt + 1)) * Vq + bn + colT * 8;
        const float* bp = bias + bn + colT * 8;
#pragma unroll
        for (int j = 0; j < 8; j += 4) {
            float4 v;
            v.x = acc[i][j + 0] + bp[j + 0];
            v.y = acc[i][j + 1] + bp[j + 1];
            v.z = acc[i][j + 2] + bp[j + 2];
            v.w = acc[i][j + 3] + bp[j + 3];
            *reinterpret_cast<float4*>(op + j) = v;
        }
    }
}

// -----------------------------------------------------------------------------
extern "C" void kernel_launch(void* const* d_in, const int* in_sizes, int n_in,
                              void* d_out, int out_size)
{
    const int*   source  = (const int*)d_in[0];
    const int*   target  = (const int*)d_in[1];
    const int*   slen    = (const int*)d_in[2];
    const float* enc_emb = (const float*)d_in[3];
    const float* eWih0 = (const float*)d_in[4];
    const float* eWhh0 = (const float*)d_in[5];
    const float* ebih0 = (const float*)d_in[6];
    const float* ebhh0 = (const float*)d_in[7];
    const float* eWih1 = (const float*)d_in[8];
    const float* eWhh1 = (const float*)d_in[9];
    const float* ebih1 = (const float*)d_in[10];
    const float* ebhh1 = (const float*)d_in[11];
    const float* dec_emb = (const float*)d_in[12];
    const float* dWih0 = (const float*)d_in[13];
    const float* dWhh0 = (const float*)d_in[14];
    const float* dbih0 = (const float*)d_in[15];
    const float* dbhh0 = (const float*)d_in[16];
    const float* dWih1 = (const float*)d_in[17];
    const float* dWhh1 = (const float*)d_in[18];
    const float* dbih1 = (const float*)d_in[19];
    const float* dbhh1 = (const float*)d_in[20];
    const float* fcW   = (const float*)d_in[21];
    const float* fcb   = (const float*)d_in[22];
    float* out = (float*)d_out;

    // h0 = h1 = 0
    zero_h_kernel<<<(Bq * Hq + 255) / 256, 256>>>();

    // precompute layer-0 input-side gates for all timesteps (gathered GEMMs)
    {
        dim3 ge(H3 / 128, Sq * Bq / 64);   // (12, 48)
        embed_gi_kernel<<<ge, 128>>>(source, Sq, Sq, enc_emb, eWih0, ebih0, 0);
        dim3 gd(H3 / 128, (Tq - 1) * Bq / 64);   // (12, 47)
        embed_gi_kernel<<<gd, 128>>>(target, Tq - 1, Tq, dec_emb, dWih0, dbih0, 1);
    }

    const int step_blocks = (Bq * (Hq / 4) * 32) / 256;   // 8192 warps -> 1024 blocks
    int cur = 0;

    // encoder recurrence (masked)
    for (int t = 0; t < Sq; t++) {
        gru_l0_step<<<step_blocks, 256>>>(cur, t, 0, eWhh0, ebhh0, slen);
        gru_l1_step<<<step_blocks, 256>>>(cur, t, 0, eWih1, ebih1, eWhh1, ebhh1, slen);
        cur ^= 1;
    }
    // decoder recurrence (unmasked), continues from encoder final carries
    for (int t = 0; t < Tq - 1; t++) {
        gru_l0_step<<<step_blocks, 256>>>(cur, t, 1, dWhh0, dbhh0, nullptr);
        gru_l1_step<<<step_blocks, 256>>>(cur, t, 1, dWih1, dbih1, dWhh1, dbhh1, nullptr);
        cur ^= 1;
    }

    // output: out[:,0,:] = 0; out[:,1:,:] = ys @ fc_W^T + fc_b
    zero_out0_kernel<<<(Bq * Vq / 4 + 255) / 256, 256>>>(out);
    dim3 gf((Tq - 1) * Bq / 64, Vq / 128);   // (47, 250)
    fc_kernel<<<gf, 128>>>(fcW, fcb, out);
}

// round 9
// speedup vs baseline: 1.1155x; 1.1155x over previous
#include <cuda_runtime.h>
#include <math.h>
#include <stdint.h>

#define Bq 64
#define Sq 48
#define Tq 48
#define Eq 256
#define Hq 512
#define Vq 32000
#define H3 1536

// ---------------- scratch (device globals; no runtime allocation) -------------
__device__ __align__(16) float g_gi_enc[Bq * Sq * H3];        // 18.9 MB
__device__ __align__(16) float g_gi_dec[Bq * (Tq - 1) * H3];  // 18.5 MB
__device__ __align__(16) float g_h0[2][Bq * Hq];
__device__ __align__(16) float g_h1[2][Bq * Hq];
__device__ __align__(16) float g_n0[Bq * Hq];
__device__ __align__(16) float g_ys[(Tq - 1) * Bq * Hq];      // 6.2 MB

__device__ __forceinline__ float sigmoidf_(float x) { return 1.0f / (1.0f + expf(-x)); }

// ---------------- init kernels ------------------------------------------------
__global__ void zero_h_kernel() {
    int i = blockIdx.x * blockDim.x + threadIdx.x;
    if (i < Bq * Hq) { g_h0[0][i] = 0.f; g_h1[0][i] = 0.f; }
}

__global__ void zero_out0_kernel(float* __restrict__ out) {
    int i = blockIdx.x * blockDim.x + threadIdx.x;   // over B*V/4
    if (i < Bq * Vq / 4) {
        int b  = i / (Vq / 4);
        int v4 = i % (Vq / 4);
        reinterpret_cast<float4*>(out + (size_t)b * Tq * Vq)[v4] = make_float4(0.f, 0.f, 0.f, 0.f);
    }
}

// ---------------- gi0 = emb[tok] @ Wih^T + bih  (gathered SGEMM) --------------
__global__ __launch_bounds__(128) void embed_gi_kernel(
    const int* __restrict__ tokens, int rowlen, int rowstride,
    const float* __restrict__ emb,
    const float* __restrict__ W,    // [H3][E] row-major
    const float* __restrict__ bias, // [H3]
    int is_dec)
{
    __shared__ float As[8][64];
    __shared__ float Bs[8][128];
    float* __restrict__ out = is_dec ? g_gi_dec : g_gi_enc;

    const int tid = threadIdx.x;
    const int bm = blockIdx.y * 64;
    const int bn = blockIdx.x * 128;

    const int a_row = tid >> 1;            // 0..63
    const int a_col = (tid & 1) << 2;      // 0 or 4
    const int m = bm + a_row;
    const int tok = tokens[(m / rowlen) * rowstride + (m % rowlen)];
    const float* a_ptr = emb + (size_t)tok * Eq;
    const float* b_ptr = W + (size_t)(bn + tid) * Eq;

    const int rowT = tid >> 4;             // 0..7
    const int colT = tid & 15;             // 0..15

    float acc[8][8];
#pragma unroll
    for (int i = 0; i < 8; i++)
#pragma unroll
        for (int j = 0; j < 8; j++) acc[i][j] = 0.f;

    for (int k0 = 0; k0 < Eq; k0 += 8) {
        float4 av  = *reinterpret_cast<const float4*>(a_ptr + k0 + a_col);
        float4 bv0 = *reinterpret_cast<const float4*>(b_ptr + k0);
        float4 bv1 = *reinterpret_cast<const float4*>(b_ptr + k0 + 4);
        As[a_col + 0][a_row] = av.x; As[a_col + 1][a_row] = av.y;
        As[a_col + 2][a_row] = av.z; As[a_col + 3][a_row] = av.w;
        Bs[0][tid] = bv0.x; Bs[1][tid] = bv0.y; Bs[2][tid] = bv0.z; Bs[3][tid] = bv0.w;
        Bs[4][tid] = bv1.x; Bs[5][tid] = bv1.y; Bs[6][tid] = bv1.z; Bs[7][tid] = bv1.w;
        __syncthreads();
#pragma unroll
        for (int k = 0; k < 8; k++) {
            float a[8], b[8];
            *reinterpret_cast<float4*>(&a[0]) = *reinterpret_cast<const float4*>(&As[k][rowT * 8]);
            *reinterpret_cast<float4*>(&a[4]) = *reinterpret_cast<const float4*>(&As[k][rowT * 8 + 4]);
            *reinterpret_cast<float4*>(&b[0]) = *reinterpret_cast<const float4*>(&Bs[k][colT * 8]);
            *reinterpret_cast<float4*>(&b[4]) = *reinterpret_cast<const float4*>(&Bs[k][colT * 8 + 4]);
#pragma unroll
            for (int i = 0; i < 8; i++)
#pragma unroll
                for (int j = 0; j < 8; j++) acc[i][j] += a[i] * b[j];
        }
        __syncthreads();
    }

#pragma unroll
    for (int i = 0; i < 8; i++) {
        int mm = bm + rowT * 8 + i;
        float* op = out + (size_t)mm * H3 + bn + colT * 8;
        const float* bp = bias + bn + colT * 8;
#pragma unroll
        for (int j = 0; j < 8; j += 4) {
            float4 v;
            v.x = acc[i][j + 0] + bp[j + 0];
            v.y = acc[i][j + 1] + bp[j + 1];
            v.z = acc[i][j + 2] + bp[j + 2];
            v.w = acc[i][j + 3] + bp[j + 3];
            *reinterpret_cast<float4*>(op + j) = v;
        }
    }
}

// ---------------- GRU layer-0 step --------------------------------------------
// warp -> (4 batch rows, 4 consecutive j). Each weight float4 feeds 4 b's ->
// 16 FMA per LDG.128 (was 4). 2048 warps -> 256 blocks.
__global__ __launch_bounds__(256) void gru_l0_step(
    int cur, int t, int is_dec,
    const float* __restrict__ Whh, const float* __restrict__ bhh,
    const int* __restrict__ slen)
{
    const int warp = (blockIdx.x * blockDim.x + threadIdx.x) >> 5;
    const int lane = threadIdx.x & 31;
    const int b0 = (warp >> 7) << 2;         // 16 b-groups of 4
    const int jbase = (warp & 127) << 2;
    const float* __restrict__ h = g_h0[cur];

    float acc[3][4][4];                      // [gate][jj][bb]
#pragma unroll
    for (int g = 0; g < 3; g++)
#pragma unroll
        for (int jj = 0; jj < 4; jj++)
#pragma unroll
            for (int bb = 0; bb < 4; bb++) acc[g][jj][bb] = 0.f;

#pragma unroll
    for (int c = 0; c < 4; c++) {
        const int idx = c * 128 + lane * 4;
        float4 hv[4];
#pragma unroll
        for (int bb = 0; bb < 4; bb++)
            hv[bb] = *reinterpret_cast<const float4*>(h + (b0 + bb) * Hq + idx);
#pragma unroll
        for (int g = 0; g < 3; g++) {
#pragma unroll
            for (int jj = 0; jj < 4; jj++) {
                float4 w4 = *reinterpret_cast<const float4*>(
                    Whh + (size_t)(g * Hq + jbase + jj) * Hq + idx);
#pragma unroll
                for (int bb = 0; bb < 4; bb++)
                    acc[g][jj][bb] += w4.x * hv[bb].x + w4.y * hv[bb].y
                                    + w4.z * hv[bb].z + w4.w * hv[bb].w;
            }
        }
    }

#pragma unroll
    for (int g = 0; g < 3; g++)
#pragma unroll
        for (int jj = 0; jj < 4; jj++)
#pragma unroll
            for (int bb = 0; bb < 4; bb++) {
                float v = acc[g][jj][bb];
#pragma unroll
                for (int o = 16; o > 0; o >>= 1) v += __shfl_xor_sync(0xffffffffu, v, o);
                acc[g][jj][bb] = v;          // lane-uniform now
            }

    const float* gi = is_dec ? (g_gi_dec + (size_t)t * H3) : (g_gi_enc + (size_t)t * H3);
    const int bstride = is_dec ? (Tq - 1) * H3 : Sq * H3;

    if (lane < 16) {
        const int b = b0 + (lane & 3);
        const int j = jbase + (lane >> 2);
        // static select chain: lane q -> acc[.][q>>2][q&3]
        float a0 = acc[0][0][0], a1 = acc[1][0][0], a2 = acc[2][0][0];
#pragma unroll
        for (int q = 1; q < 16; q++) {
            if (lane == q) { a0 = acc[0][q >> 2][q & 3];
                             a1 = acc[1][q >> 2][q & 3];
                             a2 = acc[2][q >> 2][q & 3]; }
        }
        const bool msk = slen ? (t < slen[b]) : true;
        float gir = gi[(size_t)b * bstride + j];
        float giz = gi[(size_t)b * bstride + Hq + j];
        float gin = gi[(size_t)b * bstride + 2 * Hq + j];
        float r = sigmoidf_(gir + a0 + bhh[j]);
        float z = sigmoidf_(giz + a1 + bhh[Hq + j]);
        float n = tanhf(gin + r * (a2 + bhh[2 * Hq + j]));
        float hp = h[b * Hq + j];
        float hn = (1.f - z) * n + z * hp;
        g_n0[b * Hq + j] = hn;                       // raw output feeds layer 1
        g_h0[cur ^ 1][b * Hq + j] = msk ? hn : hp;   // masked carry
    }
}

// ---------------- GRU layer-1 step --------------------------------------------
// warp -> (2 batch rows, 4 j). Fuses Wih1*n0 and Whh1*h1; each weight float4
// feeds 2 b's. 4096 warps -> 512 blocks.
__global__ __launch_bounds__(256) void gru_l1_step(
    int cur, int t, int is_dec,
    const float* __restrict__ Wih, const float* __restrict__ bih,
    const float* __restrict__ Whh, const float* __restrict__ bhh,
    const int* __restrict__ slen)
{
    const int warp = (blockIdx.x * blockDim.x + threadIdx.x) >> 5;
    const int lane = threadIdx.x & 31;
    const int b0 = (warp >> 7) << 1;         // 32 b-groups of 2
    const int jbase = (warp & 127) << 2;
    const float* __restrict__ xr = g_n0;
    const float* __restrict__ h = g_h1[cur];

    float acc[6][4][2];                      // [0..2]=Wih vs x, [3..5]=Whh vs h
#pragma unroll
    for (int g = 0; g < 6; g++)
#pragma unroll
        for (int jj = 0; jj < 4; jj++)
#pragma unroll
            for (int bb = 0; bb < 2; bb++) acc[g][jj][bb] = 0.f;

#pragma unroll
    for (int c = 0; c < 4; c++) {
        const int idx = c * 128 + lane * 4;
        float4 xv[2], hv[2];
#pragma unroll
        for (int bb = 0; bb < 2; bb++) {
            xv[bb] = *reinterpret_cast<const float4*>(xr + (b0 + bb) * Hq + idx);
            hv[bb] = *reinterpret_cast<const float4*>(h  + (b0 + bb) * Hq + idx);
        }
#pragma unroll
        for (int g = 0; g < 3; g++) {
#pragma unroll
            for (int jj = 0; jj < 4; jj++) {
                const size_t ro = (size_t)(g * Hq + jbase + jj) * Hq + idx;
                float4 wi = *reinterpret_cast<const float4*>(Wih + ro);
                float4 wh = *reinterpret_cast<const float4*>(Whh + ro);
#pragma unroll
                for (int bb = 0; bb < 2; bb++) {
                    acc[g][jj][bb]     += wi.x * xv[bb].x + wi.y * xv[bb].y
                                        + wi.z * xv[bb].z + wi.w * xv[bb].w;
                    acc[3 + g][jj][bb] += wh.x * hv[bb].x + wh.y * hv[bb].y
                                        + wh.z * hv[bb].z + wh.w * hv[bb].w;
                }
            }
        }
    }

#pragma unroll
    for (int g = 0; g < 6; g++)
#pragma unroll
        for (int jj = 0; jj < 4; jj++)
#pragma unroll
            for (int bb = 0; bb < 2; bb++) {
                float v = acc[g][jj][bb];
#pragma unroll
                for (int o = 16; o > 0; o >>= 1) v += __shfl_xor_sync(0xffffffffu, v, o);
                acc[g][jj][bb] = v;
            }

    if (lane < 8) {
        const int b = b0 + (lane & 1);
        const int j = jbase + (lane >> 1);
        float a0 = acc[0][0][0], a1 = acc[1][0][0], a2 = acc[2][0][0];
        float a3 = acc[3][0][0], a4 = acc[4][0][0], a5 = acc[5][0][0];
#pragma unroll
        for (int q = 1; q < 8; q++) {
            if (lane == q) { a0 = acc[0][q >> 1][q & 1]; a1 = acc[1][q >> 1][q & 1];
                             a2 = acc[2][q >> 1][q & 1]; a3 = acc[3][q >> 1][q & 1];
                             a4 = acc[4][q >> 1][q & 1]; a5 = acc[5][q >> 1][q & 1]; }
        }
        const bool msk = slen ? (t < slen[b]) : true;
        float r = sigmoidf_(a0 + bih[j]          + a3 + bhh[j]);
        float z = sigmoidf_(a1 + bih[Hq + j]     + a4 + bhh[Hq + j]);
        float n = tanhf(a2 + bih[2 * Hq + j] + r * (a5 + bhh[2 * Hq + j]));
        float hp = h[b * Hq + j];
        float hn = (1.f - z) * n + z * hp;
        g_h1[cur ^ 1][b * Hq + j] = msk ? hn : hp;
        if (is_dec) g_ys[((size_t)t * Bq + b) * Hq + j] = hn;
    }
}

// ---------------- final FC: logits = ys @ fc_W^T + fc_b, scattered ------------
// M=3008 (t*64+b), N=32000, K=512. BM=64, BN=128, BK=8, 128 threads, 8x8 tile.
__global__ __launch_bounds__(128) void fc_kernel(
    const float* __restrict__ W,    // [V][H]
    const float* __restrict__ bias, // [V]
    float* __restrict__ out)
{
    __shared__ float As[8][64];
    __shared__ float Bs[8][128];

    const int tid = threadIdx.x;
    const int bm = blockIdx.x * 64;
    const int bn = blockIdx.y * 128;

    const int a_row = tid >> 1;
    const int a_col = (tid & 1) << 2;
    const float* a_ptr = g_ys + (size_t)(bm + a_row) * Hq;
    const float* b_ptr = W + (size_t)(bn + tid) * Hq;

    const int rowT = tid >> 4;
    const int colT = tid & 15;

    float acc[8][8];
#pragma unroll
    for (int i = 0; i < 8; i++)
#pragma unroll
        for (int j = 0; j < 8; j++) acc[i][j] = 0.f;

    for (int k0 = 0; k0 < Hq; k0 += 8) {
        float4 av  = *reinterpret_cast<const float4*>(a_ptr + k0 + a_col);
        float4 bv0 = __ldg(reinterpret_cast<const float4*>(b_ptr + k0));
        float4 bv1 = __ldg(reinterpret_cast<const float4*>(b_ptr + k0 + 4));
        As[a_col + 0][a_row] = av.x; As[a_col + 1][a_row] = av.y;
        As[a_col + 2][a_row] = av.z; As[a_col + 3][a_row] = av.w;
        Bs[0][tid] = bv0.x; Bs[1][tid] = bv0.y; Bs[2][tid] = bv0.z; Bs[3][tid] = bv0.w;
        Bs[4][tid] = bv1.x; Bs[5][tid] = bv1.y; Bs[6][tid] = bv1.z; Bs[7][tid] = bv1.w;
        __syncthreads();
#pragma unroll
        for (int k = 0; k < 8; k++) {
            float a[8], b[8];
            *reinterpret_cast<float4*>(&a[0]) = *reinterpret_cast<const float4*>(&As[k][rowT * 8]);
            *reinterpret_cast<float4*>(&a[4]) = *reinterpret_cast<const float4*>(&As[k][rowT * 8 + 4]);
            *reinterpret_cast<float4*>(&b[0]) = *reinterpret_cast<const float4*>(&Bs[k][colT * 8]);
            *reinterpret_cast<float4*>(&b[4]) = *reinterpret_cast<const float4*>(&Bs[k][colT * 8 + 4]);
#pragma unroll
            for (int i = 0; i < 8; i++)
#pragma unroll
                for (int j = 0; j < 8; j++) acc[i][j] += a[i] * b[j];
        }
        __syncthreads();
    }

#pragma unroll
    for (int i = 0; i < 8; i++) {
        int mm = bm + rowT * 8 + i;          // = t*64 + b
        int tt = mm >> 6;
        int bb = mm & 63;
        float* op = out + ((size_t)bb * Tq + (tt + 1)) * Vq + bn + colT * 8;
        const float* bp = bias + bn + colT * 8;
#pragma unroll
        for (int j = 0; j < 8; j += 4) {
            float4 v;
            v.x = acc[i][j + 0] + bp[j + 0];
            v.y = acc[i][j + 1] + bp[j + 1];
            v.z = acc[i][j + 2] + bp[j + 2];
            v.w = acc[i][j + 3] + bp[j + 3];
            *reinterpret_cast<float4*>(op + j) = v;
        }
    }
}

// -----------------------------------------------------------------------------
extern "C" void kernel_launch(void* const* d_in, const int* in_sizes, int n_in,
                              void* d_out, int out_size)
{
    const int*   source  = (const int*)d_in[0];
    const int*   target  = (const int*)d_in[1];
    const int*   slen    = (const int*)d_in[2];
    const float* enc_emb = (const float*)d_in[3];
    const float* eWih0 = (const float*)d_in[4];
    const float* eWhh0 = (const float*)d_in[5];
    const float* ebih0 = (const float*)d_in[6];
    const float* ebhh0 = (const float*)d_in[7];
    const float* eWih1 = (const float*)d_in[8];
    const float* eWhh1 = (const float*)d_in[9];
    const float* ebih1 = (const float*)d_in[10];
    const float* ebhh1 = (const float*)d_in[11];
    const float* dec_emb = (const float*)d_in[12];
    const float* dWih0 = (const float*)d_in[13];
    const float* dWhh0 = (const float*)d_in[14];
    const float* dbih0 = (const float*)d_in[15];
    const float* dbhh0 = (const float*)d_in[16];
    const float* dWih1 = (const float*)d_in[17];
    const float* dWhh1 = (const float*)d_in[18];
    const float* dbih1 = (const float*)d_in[19];
    const float* dbhh1 = (const float*)d_in[20];
    const float* fcW   = (const float*)d_in[21];
    const float* fcb   = (const float*)d_in[22];
    float* out = (float*)d_out;

    // h0 = h1 = 0
    zero_h_kernel<<<(Bq * Hq + 255) / 256, 256>>>();

    // precompute layer-0 input-side gates for all timesteps (gathered GEMMs)
    {
        dim3 ge(H3 / 128, Sq * Bq / 64);   // (12, 48)
        embed_gi_kernel<<<ge, 128>>>(source, Sq, Sq, enc_emb, eWih0, ebih0, 0);
        dim3 gd(H3 / 128, (Tq - 1) * Bq / 64);   // (12, 47)
        embed_gi_kernel<<<gd, 128>>>(target, Tq - 1, Tq, dec_emb, dWih0, dbih0, 1);
    }

    const int l0_blocks = (16 * 128) * 32 / 256;   // 2048 warps -> 256 blocks
    const int l1_blocks = (32 * 128) * 32 / 256;   // 4096 warps -> 512 blocks
    int cur = 0;

    // encoder recurrence (masked)
    for (int t = 0; t < Sq; t++) {
        gru_l0_step<<<l0_blocks, 256>>>(cur, t, 0, eWhh0, ebhh0, slen);
        gru_l1_step<<<l1_blocks, 256>>>(cur, t, 0, eWih1, ebih1, eWhh1, ebhh1, slen);
        cur ^= 1;
    }
    // decoder recurrence (unmasked), continues from encoder final carries
    for (int t = 0; t < Tq - 1; t++) {
        gru_l0_step<<<l0_blocks, 256>>>(cur, t, 1, dWhh0, dbhh0, nullptr);
        gru_l1_step<<<l1_blocks, 256>>>(cur, t, 1, dWih1, dbih1, dWhh1, dbhh1, nullptr);
        cur ^= 1;
    }

    // output: out[:,0,:] = 0; out[:,1:,:] = ys @ fc_W^T + fc_b
    zero_out0_kernel<<<(Bq * Vq / 4 + 255) / 256, 256>>>(out);
    dim3 gf((Tq - 1) * Bq / 64, Vq / 128);   // (47, 250)
    fc_kernel<<<gf, 128>>>(fcW, fcb, out);
}

// round 12
// speedup vs baseline: 1.5260x; 1.3680x over previous
#include <cuda_runtime.h>
#include <math.h>
#include <stdint.h>

#define Bq 64
#define Sq 48
#define Tq 48
#define Eq 256
#define Hq 512
#define Vq 32000
#define H3 1536

// ---------------- scratch (device globals; no runtime allocation) -------------
__device__ __align__(16) float g_gi_enc[Bq * Sq * H3];        // 18.9 MB
__device__ __align__(16) float g_gi_dec[Bq * (Tq - 1) * H3];  // 18.5 MB
__device__ __align__(16) float g_h0[2][Bq * Hq];
__device__ __align__(16) float g_h1[2][Bq * Hq];
__device__ __align__(16) float g_n0[Bq * Hq];
__device__ __align__(16) float g_ys[(Tq - 1) * Bq * Hq];      // 6.2 MB

__device__ __forceinline__ float sigmoidf_(float x) { return 1.0f / (1.0f + expf(-x)); }

__device__ __forceinline__ uint32_t f2tf32(float f) {
    uint32_t u;
    asm("cvt.rna.tf32.f32 %0, %1;" : "=r"(u) : "f"(f));
    return u;
}

// ---------------- init kernels ------------------------------------------------
__global__ void zero_h_kernel() {
    int i = blockIdx.x * blockDim.x + threadIdx.x;
    if (i < Bq * Hq) { g_h0[0][i] = 0.f; g_h1[0][i] = 0.f; }
}

__global__ void zero_out0_kernel(float* __restrict__ out) {
    int i = blockIdx.x * blockDim.x + threadIdx.x;   // over B*V/4
    if (i < Bq * Vq / 4) {
        int b  = i / (Vq / 4);
        int v4 = i % (Vq / 4);
        reinterpret_cast<float4*>(out + (size_t)b * Tq * Vq)[v4] = make_float4(0.f, 0.f, 0.f, 0.f);
    }
}

// ---------------- gi0 = emb[tok] @ Wih^T + bih  (gathered SGEMM) --------------
__global__ __launch_bounds__(128) void embed_gi_kernel(
    const int* __restrict__ tokens, int rowlen, int rowstride,
    const float* __restrict__ emb,
    const float* __restrict__ W,    // [H3][E] row-major
    const float* __restrict__ bias, // [H3]
    int is_dec)
{
    __shared__ float As[8][64];
    __shared__ float Bs[8][128];
    float* __restrict__ out = is_dec ? g_gi_dec : g_gi_enc;

    const int tid = threadIdx.x;
    const int bm = blockIdx.y * 64;
    const int bn = blockIdx.x * 128;

    const int a_row = tid >> 1;            // 0..63
    const int a_col = (tid & 1) << 2;      // 0 or 4
    const int m = bm + a_row;
    const int tok = tokens[(m / rowlen) * rowstride + (m % rowlen)];
    const float* a_ptr = emb + (size_t)tok * Eq;
    const float* b_ptr = W + (size_t)(bn + tid) * Eq;

    const int rowT = tid >> 4;             // 0..7
    const int colT = tid & 15;             // 0..15

    float acc[8][8];
#pragma unroll
    for (int i = 0; i < 8; i++)
#pragma unroll
        for (int j = 0; j < 8; j++) acc[i][j] = 0.f;

    for (int k0 = 0; k0 < Eq; k0 += 8) {
        float4 av  = *reinterpret_cast<const float4*>(a_ptr + k0 + a_col);
        float4 bv0 = *reinterpret_cast<const float4*>(b_ptr + k0);
        float4 bv1 = *reinterpret_cast<const float4*>(b_ptr + k0 + 4);
        As[a_col + 0][a_row] = av.x; As[a_col + 1][a_row] = av.y;
        As[a_col + 2][a_row] = av.z; As[a_col + 3][a_row] = av.w;
        Bs[0][tid] = bv0.x; Bs[1][tid] = bv0.y; Bs[2][tid] = bv0.z; Bs[3][tid] = bv0.w;
        Bs[4][tid] = bv1.x; Bs[5][tid] = bv1.y; Bs[6][tid] = bv1.z; Bs[7][tid] = bv1.w;
        __syncthreads();
#pragma unroll
        for (int k = 0; k < 8; k++) {
            float a[8], b[8];
            *reinterpret_cast<float4*>(&a[0]) = *reinterpret_cast<const float4*>(&As[k][rowT * 8]);
            *reinterpret_cast<float4*>(&a[4]) = *reinterpret_cast<const float4*>(&As[k][rowT * 8 + 4]);
            *reinterpret_cast<float4*>(&b[0]) = *reinterpret_cast<const float4*>(&Bs[k][colT * 8]);
            *reinterpret_cast<float4*>(&b[4]) = *reinterpret_cast<const float4*>(&Bs[k][colT * 8 + 4]);
#pragma unroll
            for (int i = 0; i < 8; i++)
#pragma unroll
                for (int j = 0; j < 8; j++) acc[i][j] += a[i] * b[j];
        }
        __syncthreads();
    }

#pragma unroll
    for (int i = 0; i < 8; i++) {
        int mm = bm + rowT * 8 + i;
        float* op = out + (size_t)mm * H3 + bn + colT * 8;
        const float* bp = bias + bn + colT * 8;
#pragma unroll
        for (int j = 0; j < 8; j += 4) {
            float4 v;
            v.x = acc[i][j + 0] + bp[j + 0];
            v.y = acc[i][j + 1] + bp[j + 1];
            v.z = acc[i][j + 2] + bp[j + 2];
            v.w = acc[i][j + 3] + bp[j + 3];
            *reinterpret_cast<float4*>(op + j) = v;
        }
    }
}

// ---------------- GRU layer-0 step --------------------------------------------
__global__ __launch_bounds__(256) void gru_l0_step(
    int cur, int t, int is_dec,
    const float* __restrict__ Whh, const float* __restrict__ bhh,
    const int* __restrict__ slen)
{
    const int warp = (blockIdx.x * blockDim.x + threadIdx.x) >> 5;
    const int lane = threadIdx.x & 31;
    const int b0 = (warp >> 7) << 2;         // 16 b-groups of 4
    const int jbase = (warp & 127) << 2;
    const float* __restrict__ h = g_h0[cur];

    float acc[3][4][4];                      // [gate][jj][bb]
#pragma unroll
    for (int g = 0; g < 3; g++)
#pragma unroll
        for (int jj = 0; jj < 4; jj++)
#pragma unroll
            for (int bb = 0; bb < 4; bb++) acc[g][jj][bb] = 0.f;

#pragma unroll
    for (int c = 0; c < 4; c++) {
        const int idx = c * 128 + lane * 4;
        float4 hv[4];
#pragma unroll
        for (int bb = 0; bb < 4; bb++)
            hv[bb] = *reinterpret_cast<const float4*>(h + (b0 + bb) * Hq + idx);
#pragma unroll
        for (int g = 0; g < 3; g++) {
#pragma unroll
            for (int jj = 0; jj < 4; jj++) {
                float4 w4 = *reinterpret_cast<const float4*>(
                    Whh + (size_t)(g * Hq + jbase + jj) * Hq + idx);
#pragma unroll
                for (int bb = 0; bb < 4; bb++)
                    acc[g][jj][bb] += w4.x * hv[bb].x + w4.y * hv[bb].y
                                    + w4.z * hv[bb].z + w4.w * hv[bb].w;
            }
        }
    }

#pragma unroll
    for (int g = 0; g < 3; g++)
#pragma unroll
        for (int jj = 0; jj < 4; jj++)
#pragma unroll
            for (int bb = 0; bb < 4; bb++) {
                float v = acc[g][jj][bb];
#pragma unroll
                for (int o = 16; o > 0; o >>= 1) v += __shfl_xor_sync(0xffffffffu, v, o);
                acc[g][jj][bb] = v;          // lane-uniform now
            }

    const float* gi = is_dec ? (g_gi_dec + (size_t)t * H3) : (g_gi_enc + (size_t)t * H3);
    const int bstride = is_dec ? (Tq - 1) * H3 : Sq * H3;

    if (lane < 16) {
        const int b = b0 + (lane & 3);
        const int j = jbase + (lane >> 2);
        float a0 = acc[0][0][0], a1 = acc[1][0][0], a2 = acc[2][0][0];
#pragma unroll
        for (int q = 1; q < 16; q++) {
            if (lane == q) { a0 = acc[0][q >> 2][q & 3];
                             a1 = acc[1][q >> 2][q & 3];
                             a2 = acc[2][q >> 2][q & 3]; }
        }
        const bool msk = slen ? (t < slen[b]) : true;
        float gir = gi[(size_t)b * bstride + j];
        float giz = gi[(size_t)b * bstride + Hq + j];
        float gin = gi[(size_t)b * bstride + 2 * Hq + j];
        float r = sigmoidf_(gir + a0 + bhh[j]);
        float z = sigmoidf_(giz + a1 + bhh[Hq + j]);
        float n = tanhf(gin + r * (a2 + bhh[2 * Hq + j]));
        float hp = h[b * Hq + j];
        float hn = (1.f - z) * n + z * hp;
        g_n0[b * Hq + j] = hn;                       // raw output feeds layer 1
        g_h0[cur ^ 1][b * Hq + j] = msk ? hn : hp;   // masked carry
    }
}

// ---------------- GRU layer-1 step --------------------------------------------
__global__ __launch_bounds__(256) void gru_l1_step(
    int cur, int t, int is_dec,
    const float* __restrict__ Wih, const float* __restrict__ bih,
    const float* __restrict__ Whh, const float* __restrict__ bhh,
    const int* __restrict__ slen)
{
    const int warp = (blockIdx.x * blockDim.x + threadIdx.x) >> 5;
    const int lane = threadIdx.x & 31;
    const int b0 = (warp >> 7) << 1;         // 32 b-groups of 2
    const int jbase = (warp & 127) << 2;
    const float* __restrict__ xr = g_n0;
    const float* __restrict__ h = g_h1[cur];

    float acc[6][4][2];                      // [0..2]=Wih vs x, [3..5]=Whh vs h
#pragma unroll
    for (int g = 0; g < 6; g++)
#pragma unroll
        for (int jj = 0; jj < 4; jj++)
#pragma unroll
            for (int bb = 0; bb < 2; bb++) acc[g][jj][bb] = 0.f;

#pragma unroll
    for (int c = 0; c < 4; c++) {
        const int idx = c * 128 + lane * 4;
        float4 xv[2], hv[2];
#pragma unroll
        for (int bb = 0; bb < 2; bb++) {
            xv[bb] = *reinterpret_cast<const float4*>(xr + (b0 + bb) * Hq + idx);
            hv[bb] = *reinterpret_cast<const float4*>(h  + (b0 + bb) * Hq + idx);
        }
#pragma unroll
        for (int g = 0; g < 3; g++) {
#pragma unroll
            for (int jj = 0; jj < 4; jj++) {
                const size_t ro = (size_t)(g * Hq + jbase + jj) * Hq + idx;
                float4 wi = *reinterpret_cast<const float4*>(Wih + ro);
                float4 wh = *reinterpret_cast<const float4*>(Whh + ro);
#pragma unroll
                for (int bb = 0; bb < 2; bb++) {
                    acc[g][jj][bb]     += wi.x * xv[bb].x + wi.y * xv[bb].y
                                        + wi.z * xv[bb].z + wi.w * xv[bb].w;
                    acc[3 + g][jj][bb] += wh.x * hv[bb].x + wh.y * hv[bb].y
                                        + wh.z * hv[bb].z + wh.w * hv[bb].w;
                }
            }
        }
    }

#pragma unroll
    for (int g = 0; g < 6; g++)
#pragma unroll
        for (int jj = 0; jj < 4; jj++)
#pragma unroll
            for (int bb = 0; bb < 2; bb++) {
                float v = acc[g][jj][bb];
#pragma unroll
                for (int o = 16; o > 0; o >>= 1) v += __shfl_xor_sync(0xffffffffu, v, o);
                acc[g][jj][bb] = v;
            }

    if (lane < 8) {
        const int b = b0 + (lane & 1);
        const int j = jbase + (lane >> 1);
        float a0 = acc[0][0][0], a1 = acc[1][0][0], a2 = acc[2][0][0];
        float a3 = acc[3][0][0], a4 = acc[4][0][0], a5 = acc[5][0][0];
#pragma unroll
        for (int q = 1; q < 8; q++) {
            if (lane == q) { a0 = acc[0][q >> 1][q & 1]; a1 = acc[1][q >> 1][q & 1];
                             a2 = acc[2][q >> 1][q & 1]; a3 = acc[3][q >> 1][q & 1];
                             a4 = acc[4][q >> 1][q & 1]; a5 = acc[5][q >> 1][q & 1]; }
        }
        const bool msk = slen ? (t < slen[b]) : true;
        float r = sigmoidf_(a0 + bih[j]          + a3 + bhh[j]);
        float z = sigmoidf_(a1 + bih[Hq + j]     + a4 + bhh[Hq + j]);
        float n = tanhf(a2 + bih[2 * Hq + j] + r * (a5 + bhh[2 * Hq + j]));
        float hp = h[b * Hq + j];
        float hn = (1.f - z) * n + z * hp;
        g_h1[cur ^ 1][b * Hq + j] = msk ? hn : hp;
        if (is_dec) g_ys[((size_t)t * Bq + b) * Hq + j] = hn;
    }
}

// ---------------- final FC (tf32 tensor cores) --------------------------------
// D[m][n] = ys[m][:] . W[n][:] + bias[n], scattered to out[b, t+1, n].
// M=3008, N=32000, K=512. BM=64, BN=128, BK=16. 256 threads = 8 warps (2m x 4n),
// warp tile 32x32 built from mma.sync.m16n8k8 tf32 atoms (2 m-atoms x 4 n-atoms).
__global__ __launch_bounds__(256) void fc_tf32_kernel(
    const float* __restrict__ W,    // [V][H]
    const float* __restrict__ bias, // [V]
    float* __restrict__ out)
{
    __shared__ float As[64][20];    // padded stride 20: conflict-free frag loads
    __shared__ float Bs[128][20];

    const int tid  = threadIdx.x;
    const int warp = tid >> 5;
    const int lane = tid & 31;
    const int g    = lane >> 2;     // groupID 0..7
    const int tg   = lane & 3;      // threadID_in_group 0..3

    const int bm = blockIdx.x * 64;     // = t-slab (64 rows = one t)
    const int bn = blockIdx.y * 128;
    const int wm = (warp & 1) * 32;
    const int wn = (warp >> 1) * 32;

    // gmem staging indices
    const int ar = tid >> 2;            // 0..63
    const int ac = (tid & 3) << 2;      // 0,4,8,12
    const int br = tid >> 1;            // 0..127
    const int bc = (tid & 1) << 3;      // 0 or 8

    const float* a_ptr = g_ys + (size_t)(bm + ar) * Hq + ac;
    const float* b_ptr = W + (size_t)(bn + br) * Hq + bc;

    float c[2][4][4];
#pragma unroll
    for (int am = 0; am < 2; am++)
#pragma unroll
        for (int an = 0; an < 4; an++)
#pragma unroll
            for (int i = 0; i < 4; i++) c[am][an][i] = 0.f;

    for (int k0 = 0; k0 < Hq; k0 += 16) {
        // stage loads into registers (overlaps previous iteration's MMAs)
        float4 av  = *reinterpret_cast<const float4*>(a_ptr + k0);
        float4 bv0 = __ldg(reinterpret_cast<const float4*>(b_ptr + k0));
        float4 bv1 = __ldg(reinterpret_cast<const float4*>(b_ptr + k0 + 4));
        __syncthreads();   // everyone done reading smem from previous iter
        As[ar][ac + 0] = __uint_as_float(f2tf32(av.x));
        As[ar][ac + 1] = __uint_as_float(f2tf32(av.y));
        As[ar][ac + 2] = __uint_as_float(f2tf32(av.z));
        As[ar][ac + 3] = __uint_as_float(f2tf32(av.w));
        Bs[br][bc + 0] = __uint_as_float(f2tf32(bv0.x));
        Bs[br][bc + 1] = __uint_as_float(f2tf32(bv0.y));
        Bs[br][bc + 2] = __uint_as_float(f2tf32(bv0.z));
        Bs[br][bc + 3] = __uint_as_float(f2tf32(bv0.w));
        Bs[br][bc + 4] = __uint_as_float(f2tf32(bv1.x));
        Bs[br][bc + 5] = __uint_as_float(f2tf32(bv1.y));
        Bs[br][bc + 6] = __uint_as_float(f2tf32(bv1.z));
        Bs[br][bc + 7] = __uint_as_float(f2tf32(bv1.w));
        __syncthreads();

#pragma unroll
        for (int ks = 0; ks < 2; ks++) {
            const int kk = ks * 8;
            uint32_t a[2][4];
#pragma unroll
            for (int am = 0; am < 2; am++) {
                const int r0 = wm + am * 16;
                a[am][0] = __float_as_uint(As[r0 + g    ][kk + tg    ]);
                a[am][1] = __float_as_uint(As[r0 + g + 8][kk + tg    ]);
                a[am][2] = __float_as_uint(As[r0 + g    ][kk + tg + 4]);
                a[am][3] = __float_as_uint(As[r0 + g + 8][kk + tg + 4]);
            }
            uint32_t b[4][2];
#pragma unroll
            for (int an = 0; an < 4; an++) {
                const int n0 = wn + an * 8;
                b[an][0] = __float_as_uint(Bs[n0 + g][kk + tg    ]);
                b[an][1] = __float_as_uint(Bs[n0 + g][kk + tg + 4]);
            }
#pragma unroll
            for (int am = 0; am < 2; am++)
#pragma unroll
                for (int an = 0; an < 4; an++) {
                    asm volatile(
                        "mma.sync.aligned.m16n8k8.row.col.f32.tf32.tf32.f32 "
                        "{%0,%1,%2,%3}, {%4,%5,%6,%7}, {%8,%9}, {%0,%1,%2,%3};"
                        : "+f"(c[am][an][0]), "+f"(c[am][an][1]),
                          "+f"(c[am][an][2]), "+f"(c[am][an][3])
                        : "r"(a[am][0]), "r"(a[am][1]), "r"(a[am][2]), "r"(a[am][3]),
                          "r"(b[an][0]), "r"(b[an][1]));
                }
        }
    }

    // epilogue: scatter to out[b, t+1, n] with bias
#pragma unroll
    for (int am = 0; am < 2; am++) {
#pragma unroll
        for (int an = 0; an < 4; an++) {
            const int n0 = bn + wn + an * 8 + tg * 2;
            const float bx = __ldg(bias + n0);
            const float by = __ldg(bias + n0 + 1);
#pragma unroll
            for (int rr = 0; rr < 2; rr++) {
                const int mm = bm + wm + am * 16 + g + rr * 8;   // = t*64 + b
                const int tt = mm >> 6;
                const int bb = mm & 63;
                float2 v;
                v.x = c[am][an][rr * 2 + 0] + bx;
                v.y = c[am][an][rr * 2 + 1] + by;
                *reinterpret_cast<float2*>(
                    out + ((size_t)bb * Tq + (tt + 1)) * Vq + n0) = v;
            }
        }
    }
}

// -----------------------------------------------------------------------------
extern "C" void kernel_launch(void* const* d_in, const int* in_sizes, int n_in,
                              void* d_out, int out_size)
{
    const int*   source  = (const int*)d_in[0];
    const int*   target  = (const int*)d_in[1];
    const int*   slen    = (const int*)d_in[2];
    const float* enc_emb = (const float*)d_in[3];
    const float* eWih0 = (const float*)d_in[4];
    const float* eWhh0 = (const float*)d_in[5];
    const float* ebih0 = (const float*)d_in[6];
    const float* ebhh0 = (const float*)d_in[7];
    const float* eWih1 = (const float*)d_in[8];
    const float* eWhh1 = (const float*)d_in[9];
    const float* ebih1 = (const float*)d_in[10];
    const float* ebhh1 = (const float*)d_in[11];
    const float* dec_emb = (const float*)d_in[12];
    const float* dWih0 = (const float*)d_in[13];
    const float* dWhh0 = (const float*)d_in[14];
    const float* dbih0 = (const float*)d_in[15];
    const float* dbhh0 = (const float*)d_in[16];
    const float* dWih1 = (const float*)d_in[17];
    const float* dWhh1 = (const float*)d_in[18];
    const float* dbih1 = (const float*)d_in[19];
    const float* dbhh1 = (const float*)d_in[20];
    const float* fcW   = (const float*)d_in[21];
    const float* fcb   = (const float*)d_in[22];
    float* out = (float*)d_out;

    // h0 = h1 = 0
    zero_h_kernel<<<(Bq * Hq + 255) / 256, 256>>>();

    // precompute layer-0 input-side gates for all timesteps (gathered GEMMs)
    {
        dim3 ge(H3 / 128, Sq * Bq / 64);   // (12, 48)
        embed_gi_kernel<<<ge, 128>>>(source, Sq, Sq, enc_emb, eWih0, ebih0, 0);
        dim3 gd(H3 / 128, (Tq - 1) * Bq / 64);   // (12, 47)
        embed_gi_kernel<<<gd, 128>>>(target, Tq - 1, Tq, dec_emb, dWih0, dbih0, 1);
    }

    const int l0_blocks = (16 * 128) * 32 / 256;   // 2048 warps -> 256 blocks
    const int l1_blocks = (32 * 128) * 32 / 256;   // 4096 warps -> 512 blocks
    int cur = 0;

    // encoder recurrence (masked)
    for (int t = 0; t < Sq; t++) {
        gru_l0_step<<<l0_blocks, 256>>>(cur, t, 0, eWhh0, ebhh0, slen);
        gru_l1_step<<<l1_blocks, 256>>>(cur, t, 0, eWih1, ebih1, eWhh1, ebhh1, slen);
        cur ^= 1;
    }
    // decoder recurrence (unmasked), continues from encoder final carries
    for (int t = 0; t < Tq - 1; t++) {
        gru_l0_step<<<l0_blocks, 256>>>(cur, t, 1, dWhh0, dbhh0, nullptr);
        gru_l1_step<<<l1_blocks, 256>>>(cur, t, 1, dWih1, dbih1, dWhh1, dbhh1, nullptr);
        cur ^= 1;
    }

    // output: out[:,0,:] = 0; out[:,1:,:] = ys @ fc_W^T + fc_b (tf32 MMA)
    zero_out0_kernel<<<(Bq * Vq / 4 + 255) / 256, 256>>>(out);
    dim3 gf((Tq - 1) * Bq / 64, Vq / 128);   // (47, 250)
    fc_tf32_kernel<<<gf, 256>>>(fcW, fcb, out);
}